// round 4
// baseline (speedup 1.0000x reference)
#include <cuda_runtime.h>
#include <cuda.h>
#include <cstdint>

// LbpBlock: out = concat([x, pad(x_cat)], ch axis)
//   y[n,o,h,w] = sum_c x[n,c,h,w]*conv_w[o,c]   (c=3, o=64)
//   x_cat interior = sum_l H(y_c - y_shift_l) * exp(w[o,l]), zero border.
// x: (8,3,256,256) f32, conv_w: (64,3), w: (64,8) -> out: (8,67,256,256)

#define NN   8
#define CIN  3
#define OCH  64
#define HH   256
#define WW   256
#define TH   16
#define TW   64
#define OC   4
#define NCHUNK (OCH / OC)        // 16
#define HALO_H (TH + 2)          // 18
#define HALO_W (TW + 2)          // 66
#define HALO_N (HALO_H * HALO_W) // 1188
#define CP   74                  // swizzled float4 row pitch (sw(65)=73)
#define PLANE (HH * WW)
#define NSTG 3                   // TMA staging ring depth

struct SmemLayout {
    float4 sy[2][HALO_H][CP];          // 42624 B (128B-aligned start)
    float  stg[NSTG][OC][TH][TW];      // 49152 B (offset 42624, 128B-aligned)
    float  sew[OCH][8];                // 2048 B
    float4 scw4[OCH];                  // 1024 B
};                                      // 94848 B total

__device__ __forceinline__ int sw(int c) { return c + (c >> 3); }

__device__ __forceinline__ uint32_t smem_u32(const void* p) {
    uint32_t a;
    asm("{ .reg .u64 t; cvta.to.shared.u64 t, %1; cvt.u32.u64 %0, t; }"
        : "=r"(a) : "l"(p));
    return a;
}

__global__ __launch_bounds__(256, 2)
void lbp_main(const float* __restrict__ x,
              const float* __restrict__ cw,
              const float* __restrict__ w,
              float* __restrict__ out,
              const __grid_constant__ CUtensorMap tmap)
{
    extern __shared__ unsigned char smraw[];
    SmemLayout* sm = (SmemLayout*)smraw;

    const int tid = threadIdx.x;
    const int n   = blockIdx.z;
    const int h0  = blockIdx.y * TH;
    const int w0  = blockIdx.x * TW;

    for (int i = tid; i < OCH * 8; i += 256)
        sm->sew[i >> 3][i & 7] = __expf(w[i]);
    for (int i = tid; i < OCH; i += 256)
        sm->scw4[i] = make_float4(cw[3 * i], cw[3 * i + 1], cw[3 * i + 2], 0.f);

    // ---- x halo cached in registers (up to 5 px / thread) ----
    float xr[5][3];
    int   syoff[5];
    #pragma unroll
    for (int k = 0; k < 5; k++) {
        const int p = tid + k * 256;
        const int r = p / HALO_W;
        const int c = p - r * HALO_W;
        syoff[k] = r * CP + sw(c);
        float v0 = 0.f, v1 = 0.f, v2 = 0.f;
        if (p < HALO_N) {
            const int gh = h0 - 1 + r;
            const int gw = w0 - 1 + c;
            if ((unsigned)gh < HH && (unsigned)gw < WW) {
                const int base = (n * CIN * HH + gh) * WW + gw;
                v0 = x[base];
                v1 = x[base + PLANE];
                v2 = x[base + 2 * PLANE];
            }
        }
        xr[k][0] = v0; xr[k][1] = v1; xr[k][2] = v2;
    }

    // ---- fused copy: x -> out channels [0,3) for this tile ----
    {
        const float4* xs = (const float4*)(x + n * CIN * PLANE);
        float4*       od = (float4*)(out + n * 67 * PLANE);
        #pragma unroll
        for (int k = 0; k < 3; k++) {
            const int f  = tid + k * 256;               // 768 float4 per tile
            const int c  = f >> 8;
            const int rr = (f & 255) >> 4;
            const int cc = f & 15;
            const int idx = c * (PLANE / 4) + (h0 + rr) * (WW / 4) + (w0 / 4) + cc;
            od[idx] = xs[idx];
        }
    }
    __syncthreads();   // scw4/sew visible

    // ---- phase 1 for chunk 0 into buffer 0 ----
    {
        const float4 c0 = sm->scw4[0], c1 = sm->scw4[1];
        const float4 c2 = sm->scw4[2], c3 = sm->scw4[3];
        #pragma unroll
        for (int k = 0; k < 5; k++) {
            if (tid + k * 256 < HALO_N) {
                const float x0 = xr[k][0], x1 = xr[k][1], x2 = xr[k][2];
                float4 v;
                v.x = fmaf(x2, c0.z, fmaf(x1, c0.y, x0 * c0.x));
                v.y = fmaf(x2, c1.z, fmaf(x1, c1.y, x0 * c1.x));
                v.z = fmaf(x2, c2.z, fmaf(x1, c2.y, x0 * c2.x));
                v.w = fmaf(x2, c3.z, fmaf(x1, c3.y, x0 * c3.x));
                ((float4*)sm->sy[0])[syoff[k]] = v;
            }
        }
    }
    __syncthreads();

    const int mc   = tid & 15;          // col group (4 px)
    const int mr   = tid >> 4;          // row in tile
    const int oh   = h0 + mr;
    const int owbase = w0 + mc * 4;
    const int sc0  = mc * 4;
    const bool hv  = ((unsigned)(oh - 1) < (unsigned)(HH - 2));

    for (int ch = 0; ch < NCHUNK; ch++) {
        const int o0 = ch * OC;
        float4 (*cur)[CP] = sm->sy[ch & 1];
        float4 (*nxt)[CP] = sm->sy[(ch & 1) ^ 1];
        const int sb = ch % NSTG;       // staging buffer

        // ring safety: staging buffer (ch) was last read by TMA group (ch-3).
        // tid0's wait here (before this iter's barrier) guarantees, via the
        // barrier of iter ch, that all threads at iter ch+1 see groups <= ch-2
        // complete -> buffer (ch+1)%3 (reader ch-2) is free. For THIS iter,
        // the barrier of iter ch-1 (after tid0's wait at ch-1) gave <= ch-3. OK.
        if (tid == 0)
            asm volatile("cp.async.bulk.wait_group 1;" ::: "memory");

        // ---- window batch 1: halo columns sc0..sc0+3, 3 rows ----
        float4 c0a[3], c1a[3], c2a[3], c3a[3];
        #pragma unroll
        for (int r = 0; r < 3; r++) {
            c0a[r] = cur[mr + r][sw(sc0 + 0)];
            c1a[r] = cur[mr + r][sw(sc0 + 1)];
            c2a[r] = cur[mr + r][sw(sc0 + 2)];
            c3a[r] = cur[mr + r][sw(sc0 + 3)];
        }

        // ---- phase 1 for next chunk (reg FMA + STS; hides LDS latency) ----
        if (ch + 1 < NCHUNK) {
            const int q0 = (ch + 1) * OC;
            const float4 w0r = sm->scw4[q0],     w1r = sm->scw4[q0 + 1];
            const float4 w2r = sm->scw4[q0 + 2], w3r = sm->scw4[q0 + 3];
            #pragma unroll
            for (int k = 0; k < 5; k++) {
                if (tid + k * 256 < HALO_N) {
                    const float x0 = xr[k][0], x1 = xr[k][1], x2 = xr[k][2];
                    float4 v;
                    v.x = fmaf(x2, w0r.z, fmaf(x1, w0r.y, x0 * w0r.x));
                    v.y = fmaf(x2, w1r.z, fmaf(x1, w1r.y, x0 * w1r.x));
                    v.z = fmaf(x2, w2r.z, fmaf(x1, w2r.y, x0 * w2r.x));
                    v.w = fmaf(x2, w3r.z, fmaf(x1, w3r.y, x0 * w3r.x));
                    ((float4*)nxt)[syoff[k]] = v;
                }
            }
        }

        // ---- per-chunk exp weights ----
        float ew[OC][8];
        #pragma unroll
        for (int oc = 0; oc < OC; oc++) {
            const float4 e0 = *(const float4*)&sm->sew[o0 + oc][0];
            const float4 e1 = *(const float4*)&sm->sew[o0 + oc][4];
            ew[oc][0] = e0.x; ew[oc][1] = e0.y; ew[oc][2] = e0.z; ew[oc][3] = e0.w;
            ew[oc][4] = e1.x; ew[oc][5] = e1.y; ew[oc][6] = e1.z; ew[oc][7] = e1.w;
        }

        float res[OC][4];

        #define ACC(S, L) { const float4 s_ = (S);       \
            if (ce.x > s_.x) a0 += ew[0][L];             \
            if (ce.y > s_.y) a1 += ew[1][L];             \
            if (ce.z > s_.z) a2 += ew[2][L];             \
            if (ce.w > s_.w) a3 += ew[3][L]; }

        #define PX(jj, Wl, Wc, Wr) {                                        \
            const float4 ce = Wc[1];                                        \
            float a0 = 0.f, a1 = 0.f, a2 = 0.f, a3 = 0.f;                   \
            ACC(Wl[0], 0) ACC(Wc[0], 1) ACC(Wr[0], 2)                       \
            ACC(Wl[1], 3) ACC(Wl[2], 4) ACC(Wc[2], 5)                       \
            ACC(Wr[2], 6) ACC(Wr[1], 7)                                     \
            const int ow = owbase + jj;                                     \
            const bool v = hv && ((unsigned)(ow - 1) < (unsigned)(WW - 2)); \
            res[0][jj] = v ? a0 : 0.f;                                      \
            res[1][jj] = v ? a1 : 0.f;                                      \
            res[2][jj] = v ? a2 : 0.f;                                      \
            res[3][jj] = v ? a3 : 0.f;                                      \
        }

        PX(0, c0a, c1a, c2a)
        PX(1, c1a, c2a, c3a)

        // ---- window batch 2: halo columns sc0+4, sc0+5 ----
        float4 c4a[3], c5a[3];
        #pragma unroll
        for (int r = 0; r < 3; r++) {
            c4a[r] = cur[mr + r][sw(sc0 + 4)];
            c5a[r] = cur[mr + r][sw(sc0 + 5)];
        }

        PX(2, c2a, c3a, c4a)
        PX(3, c3a, c4a, c5a)
        #undef PX
        #undef ACC

        // ---- stage results in shared (contiguous per channel row) ----
        #pragma unroll
        for (int oc = 0; oc < OC; oc++)
            *(float4*)&sm->stg[sb][oc][mr][mc * 4] =
                make_float4(res[oc][0], res[oc][1], res[oc][2], res[oc][3]);

        __syncthreads();   // staging + nxt-sy complete; tid0's wait observed

        // ---- one TMA store for the whole 16x64x4 chunk tile ----
        if (tid == 0) {
            asm volatile("fence.proxy.async.shared::cta;" ::: "memory");
            const uint32_t sa = smem_u32(&sm->stg[sb][0][0][0]);
            const int cz = n * 67 + 3 + o0;
            asm volatile(
                "cp.async.bulk.tensor.3d.global.shared::cta.tile.bulk_group "
                "[%0, {%1, %2, %3}], [%4];"
                :: "l"(&tmap), "r"(w0), "r"(h0), "r"(cz), "r"(sa)
                : "memory");
            asm volatile("cp.async.bulk.commit_group;" ::: "memory");
        }
    }

    if (tid == 0)
        asm volatile("cp.async.bulk.wait_group 0;" ::: "memory");
}

typedef CUresult (*PFN_encodeTiled)(
    CUtensorMap*, CUtensorMapDataType, cuuint32_t, void*,
    const cuuint64_t*, const cuuint64_t*, const cuuint32_t*, const cuuint32_t*,
    CUtensorMapInterleave, CUtensorMapSwizzle, CUtensorMapL2promotion,
    CUtensorMapFloatOOBfill);

extern "C" void kernel_launch(void* const* d_in, const int* in_sizes, int n_in,
                              void* d_out, int out_size)
{
    const float* x  = (const float*)d_in[0];
    const float* cw = (const float*)d_in[1];
    const float* w  = (const float*)d_in[2];
    float* out = (float*)d_out;

    // driver entry point via cudart (no -lcuda needed)
    PFN_encodeTiled enc = nullptr;
    cudaDriverEntryPointQueryResult qr;
#if CUDART_VERSION >= 12050
    cudaGetDriverEntryPointByVersion("cuTensorMapEncodeTiled", (void**)&enc,
                                     12000, cudaEnableDefault, &qr);
#else
    cudaGetDriverEntryPoint("cuTensorMapEncodeTiled", (void**)&enc,
                            cudaEnableDefault, &qr);
#endif

    // out viewed as 3D: (w=256, h=256, z=n*67+ch = 536), f32
    CUtensorMap tmap;
    cuuint64_t dims[3]    = {WW, HH, (cuuint64_t)NN * 67};
    cuuint64_t strides[2] = {(cuuint64_t)WW * 4, (cuuint64_t)PLANE * 4};
    cuuint32_t box[3]     = {TW, TH, OC};
    cuuint32_t es[3]      = {1, 1, 1};
    enc(&tmap, CU_TENSOR_MAP_DATA_TYPE_FLOAT32, 3, (void*)out,
        dims, strides, box, es,
        CU_TENSOR_MAP_INTERLEAVE_NONE, CU_TENSOR_MAP_SWIZZLE_NONE,
        CU_TENSOR_MAP_L2_PROMOTION_L2_128B, CU_TENSOR_MAP_FLOAT_OOB_FILL_NONE);

    const int smbytes = (int)sizeof(SmemLayout);
    cudaFuncSetAttribute(lbp_main, cudaFuncAttributeMaxDynamicSharedMemorySize,
                         smbytes);

    dim3 grid(WW / TW, HH / TH, NN);   // (4, 16, 8) = 512 blocks
    lbp_main<<<grid, 256, smbytes>>>(x, cw, w, out, tmap);
}

// round 5
// speedup vs baseline: 1.0556x; 1.0556x over previous
#include <cuda_runtime.h>

// LbpBlock: out = concat([x, pad(x_cat)], ch axis)
//   y[n,o,h,w] = sum_c x[n,c,h,w]*conv_w[o,c]   (c=3, o=64)
//   x_cat interior = sum_l H(y_c - y_shift_l) * exp(w[o,l]), zero border.
// x: (8,3,256,256) f32, conv_w: (64,3), w: (64,8) -> out: (8,67,256,256)

#define NN   8
#define CIN  3
#define OCH  64
#define HH   256
#define WW   256
#define TH   32
#define TW   64
#define NCHUNK 16                // 4 channels per chunk
#define HALO_H (TH + 2)          // 34
#define HALO_W (TW + 2)          // 66
#define HALO_N (HALO_H * HALO_W) // 2244
#define XRN  9                   // ceil(2244/256)
#define CP   74                  // swizzled float4 row pitch (sw(65)=73)
#define PLANE (HH * WW)

struct SmemLayout {
    float4 sy[2][HALO_H][CP];    // 80512 B, double-buffered y (4ch packed)
    float  sew[OCH][8];          // exp(w)
    float4 scw4[OCH];            // conv_w rows
};                                // 83584 B

__device__ __forceinline__ int sw(int c) { return c + (c >> 3); }

__global__ __launch_bounds__(256, 2)
void lbp_main(const float* __restrict__ x,
              const float* __restrict__ cw,
              const float* __restrict__ w,
              float* __restrict__ out)
{
    extern __shared__ unsigned char smraw[];
    SmemLayout* sm = (SmemLayout*)smraw;

    const int tid = threadIdx.x;
    const int n   = blockIdx.z;
    const int h0  = blockIdx.y * TH;
    const int w0  = blockIdx.x * TW;

    for (int i = tid; i < OCH * 8; i += 256)
        sm->sew[i >> 3][i & 7] = __expf(w[i]);
    if (tid < OCH)
        sm->scw4[tid] = make_float4(cw[3 * tid], cw[3 * tid + 1],
                                    cw[3 * tid + 2], 0.f);

    // ---- x halo cached in registers (up to 9 px / thread) ----
    float xr[XRN][3];
    int   soff[XRN];
    #pragma unroll
    for (int k = 0; k < XRN; k++) {
        const int p = tid + k * 256;
        const int r = p / HALO_W;
        const int c = p - r * HALO_W;
        soff[k] = r * CP + sw(c);
        float v0 = 0.f, v1 = 0.f, v2 = 0.f;
        if (p < HALO_N) {
            const int gh = h0 - 1 + r;
            const int gw = w0 - 1 + c;
            if ((unsigned)gh < HH && (unsigned)gw < WW) {
                const int b = (n * CIN * HH + gh) * WW + gw;
                v0 = x[b];
                v1 = x[b + PLANE];
                v2 = x[b + 2 * PLANE];
            }
        }
        xr[k][0] = v0; xr[k][1] = v1; xr[k][2] = v2;
    }

    // ---- fused copy: x -> out channels [0,3) for this tile ----
    {
        const float4* xs = (const float4*)(x + n * CIN * PLANE);
        float4*       od = (float4*)(out + n * 67 * PLANE);
        #pragma unroll
        for (int k = 0; k < 6; k++) {               // 1536 float4 per tile
            const int f   = tid + k * 256;
            const int c   = f >> 9;                 // 512 f4 per channel-tile
            const int rem = f & 511;
            const int rr  = rem >> 4;
            const int cc  = rem & 15;
            const int idx = c * (PLANE / 4) + (h0 + rr) * (WW / 4)
                          + (w0 / 4) + cc;
            od[idx] = xs[idx];
        }
    }
    __syncthreads();   // scw4/sew visible

    // ---- phase 1: y halo for chunk q (pure register FMA + STS) ----
    auto phase1 = [&](int q, float4 (*dst)[CP]) {
        const float4 c0 = sm->scw4[4 * q],     c1 = sm->scw4[4 * q + 1];
        const float4 c2 = sm->scw4[4 * q + 2], c3 = sm->scw4[4 * q + 3];
        #pragma unroll
        for (int k = 0; k < XRN; k++) {
            if (tid + k * 256 < HALO_N) {
                const float a = xr[k][0], b = xr[k][1], d = xr[k][2];
                float4 v;
                v.x = fmaf(d, c0.z, fmaf(b, c0.y, a * c0.x));
                v.y = fmaf(d, c1.z, fmaf(b, c1.y, a * c1.x));
                v.z = fmaf(d, c2.z, fmaf(b, c2.y, a * c2.x));
                v.w = fmaf(d, c3.z, fmaf(b, c3.y, a * c3.x));
                ((float4*)dst)[soff[k]] = v;
            }
        }
    };

    phase1(0, sm->sy[0]);
    __syncthreads();

    // thread -> 2 rows x 4 cols micro-tile
    const int mc  = tid & 15;                 // col group (4 px)
    const int mrg = tid >> 4;                 // row pair (0..15)
    const int hr0 = 2 * mrg;                  // top window halo row
    const int sc0 = 4 * mc;                   // window halo col base
    const int oh0 = h0 + 2 * mrg;
    const int owbase = w0 + 4 * mc;

    for (int ch = 0; ch < NCHUNK; ch++) {
        const int o0 = 4 * ch;
        float4 (*cur)[CP] = sm->sy[ch & 1];
        float4 (*nxt)[CP] = sm->sy[(ch & 1) ^ 1];

        #define LDS2(r, c, p) (((const float2*)&cur[r][sw(c)])[p])

        #pragma unroll
        for (int p = 0; p < 2; p++) {         // channel pair within chunk
            // rolling 3-row window of float2 (2 channels)
            float2 t0[6], t1[6], t2[6];
            #pragma unroll
            for (int c = 0; c < 6; c++) {
                t0[c] = LDS2(hr0,     sc0 + c, p);
                t1[c] = LDS2(hr0 + 1, sc0 + c, p);
                t2[c] = LDS2(hr0 + 2, sc0 + c, p);
            }

            // overlap next chunk's conv while window loads are in flight
            if (p == 0 && ch + 1 < NCHUNK)
                phase1(ch + 1, nxt);

            const int cA = o0 + 2 * p;        // first channel of pair
            float e0[8], e1[8];
            {
                const float4 u0 = *(const float4*)&sm->sew[cA][0];
                const float4 u1 = *(const float4*)&sm->sew[cA][4];
                e0[0] = u0.x; e0[1] = u0.y; e0[2] = u0.z; e0[3] = u0.w;
                e0[4] = u1.x; e0[5] = u1.y; e0[6] = u1.z; e0[7] = u1.w;
                const float4 v0 = *(const float4*)&sm->sew[cA + 1][0];
                const float4 v1 = *(const float4*)&sm->sew[cA + 1][4];
                e1[0] = v0.x; e1[1] = v0.y; e1[2] = v0.z; e1[3] = v0.w;
                e1[4] = v1.x; e1[5] = v1.y; e1[6] = v1.z; e1[7] = v1.w;
            }

            #pragma unroll
            for (int pr = 0; pr < 2; pr++) {  // the 2 pixel rows
                if (pr == 1) {
                    #pragma unroll
                    for (int c = 0; c < 6; c++) {
                        t0[c] = t1[c];
                        t1[c] = t2[c];
                        t2[c] = LDS2(hr0 + 3, sc0 + c, p);
                    }
                }
                const int oh = oh0 + pr;
                const bool hv = ((unsigned)(oh - 1) < (unsigned)(HH - 2));

                float rA[4], rB[4];
                #pragma unroll
                for (int jj = 0; jj < 4; jj++) {
                    const float2 ce = t1[jj + 1];
                    float a0 = 0.f, a1 = 0.f;

                    #define ACC(S, L) { const float2 s_ = (S);   \
                        if (ce.x > s_.x) a0 += e0[L];            \
                        if (ce.y > s_.y) a1 += e1[L]; }

                    // TL, T, TR, L, BL, B, BR, R (reference shift order)
                    ACC(t0[jj    ], 0)
                    ACC(t0[jj + 1], 1)
                    ACC(t0[jj + 2], 2)
                    ACC(t1[jj    ], 3)
                    ACC(t2[jj    ], 4)
                    ACC(t2[jj + 1], 5)
                    ACC(t2[jj + 2], 6)
                    ACC(t1[jj + 2], 7)
                    #undef ACC

                    const int ow = owbase + jj;
                    const bool v = hv &&
                        ((unsigned)(ow - 1) < (unsigned)(WW - 2));
                    rA[jj] = v ? a0 : 0.f;
                    rB[jj] = v ? a1 : 0.f;
                }

                // coalesced float4 stores (2 channels x 4 px)
                const int ob = ((n * 67 + 3 + cA) * HH + oh) * WW + owbase;
                *(float4*)(out + ob        ) = make_float4(rA[0], rA[1], rA[2], rA[3]);
                *(float4*)(out + ob + PLANE) = make_float4(rB[0], rB[1], rB[2], rB[3]);
            }
        }
        #undef LDS2

        __syncthreads();   // nxt writes complete; cur free for next chunk
    }
}

extern "C" void kernel_launch(void* const* d_in, const int* in_sizes, int n_in,
                              void* d_out, int out_size)
{
    const float* x  = (const float*)d_in[0];
    const float* cw = (const float*)d_in[1];
    const float* w  = (const float*)d_in[2];
    float* out = (float*)d_out;

    const int smbytes = (int)sizeof(SmemLayout);   // 83584
    cudaFuncSetAttribute(lbp_main, cudaFuncAttributeMaxDynamicSharedMemorySize,
                         smbytes);

    dim3 grid(WW / TW, HH / TH, NN);   // (4, 8, 8) = 256 blocks
    lbp_main<<<grid, 256, smbytes>>>(x, cw, w, out);
}